// round 16
// baseline (speedup 1.0000x reference)
#include <cuda_runtime.h>
#include <cuda_fp16.h>
#include <math.h>
#include <stdint.h>

constexpr int B_  = 16;
constexpr int H_  = 1024;
constexpr int CO_ = 512;
constexpr int NV_ = 2048;
constexpr int NQ_ = 2048;

constexpr size_t PQ  = (size_t)(NQ_/2) * H_;
constexpr size_t PQT = (size_t)(H_/2) * NQ_;
constexpr size_t PV  = (size_t)(H_/2) * NV_;
constexpr size_t PVT = (size_t)(NV_/2) * H_;
constexpr size_t PW  = (size_t)(H_/2) * H_;
constexpr size_t PWC = (size_t)(H_/2) * CO_;
constexpr size_t PNC = (size_t)(NQ_/2) * CO_;
constexpr size_t PHC = (size_t)(H_/2) * CO_;

__device__ uint32_t g_Qp  [PQ  * B_], g_Qph [PQ  * B_];
__device__ uint32_t g_Qtp [PQT * B_], g_Qtph[PQT * B_];
__device__ uint32_t g_Vp  [PV  * B_], g_Vph [PV  * B_];
__device__ uint32_t g_Vtp [PVT * B_], g_Vtph[PVT * B_];
__device__ uint32_t g_Wbp [PW], g_Wbph[PW], g_Wbtp[PW], g_Wbtph[PW];
__device__ uint32_t g_WqTp[PWC], g_WqTph[PWC], g_WvTp[PWC], g_WvTph[PWC];
__device__ uint32_t g_T1p [PNC * B_], g_T1ph[PNC * B_];
__device__ uint32_t g_T2p [PNC * B_], g_T2ph[PNC * B_];
__device__ uint32_t g_PvTp[PHC * B_], g_PvTph[PHC * B_];
__device__ uint32_t g_PqTp[PHC * B_], g_PqTph[PHC * B_];
__device__ uint32_t g_RvTp[PHC * B_], g_RvTph[PHC * B_];
__device__ uint32_t g_RqTp[PHC * B_], g_RqTph[PHC * B_];

__device__ float g_T1 [(size_t)B_ * NQ_ * CO_];
__device__ float g_T2 [(size_t)B_ * NV_ * CO_];
__device__ float g_MvT[(size_t)B_ * NV_ * CO_];
__device__ float g_MqT[(size_t)B_ * NQ_ * CO_];
__device__ float g_logv[(size_t)B_ * NV_], g_logq[(size_t)B_ * NQ_];

__device__ __forceinline__ uint32_t smem_u32(const void* p) {
    uint32_t a;
    asm("{ .reg .u64 t; cvta.to.shared.u64 t, %1; cvt.u32.u64 %0, t; }" : "=r"(a) : "l"(p));
    return a;
}
#define CPA16(dst, src) \
    asm volatile("cp.async.cg.shared.global [%0], [%1], 16;" :: "r"(dst), "l"(src))
#define CP_COMMIT() asm volatile("cp.async.commit_group;" ::: "memory")
#define CP_WAIT1()  asm volatile("cp.async.wait_group 1;" ::: "memory")

__device__ __forceinline__ void pack2(float x0, float x1, uint32_t& u0, uint32_t& u1) {
    __half a0 = __float2half_rn(x0), a1 = __float2half_rn(x1);
    float r0 = x0 - __half2float(a0), r1 = x1 - __half2float(a1);
    __half b0 = __float2half_rn(r0), b1 = __float2half_rn(r1);
    u0 = (uint32_t)__half_as_ushort(a0) | ((uint32_t)__half_as_ushort(a1) << 16);
    u1 = (uint32_t)__half_as_ushort(b0) | ((uint32_t)__half_as_ushort(b1) << 16);
}
__device__ __forceinline__ void mma16(float* c, const uint32_t* a, const uint32_t* b) {
    asm volatile(
        "mma.sync.aligned.m16n8k16.row.col.f32.f16.f16.f32 "
        "{%0,%1,%2,%3}, {%4,%5,%6,%7}, {%8,%9}, {%0,%1,%2,%3};"
        : "+f"(c[0]), "+f"(c[1]), "+f"(c[2]), "+f"(c[3])
        : "r"(a[0]), "r"(a[1]), "r"(a[2]), "r"(a[3]), "r"(b[0]), "r"(b[1]));
}

// ---------------------------------------------------------------------------
// Paired GEMM (two same-shape C=A^T*B problems per launch; z>=B_ -> set1).
// EPI bit0: fp32 C (acc*outScale). EPI bit1: packed hi/lo (acc*packScale).
// ---------------------------------------------------------------------------
constexpr int SROW = 136;
constexpr int TILE_U = 16 * SROW;
constexpr int STG_U = 4 * TILE_U;
constexpr int SMEM_MMA = 3 * STG_U * 4;    // 104448 B

template <int EPI>
__global__ __launch_bounds__(256, 2)
void gemm_pair(const uint32_t* __restrict__ Ah0, const uint32_t* __restrict__ Al0,
               const uint32_t* __restrict__ Bh0, const uint32_t* __restrict__ Bl0,
               const uint32_t* __restrict__ Ah1, const uint32_t* __restrict__ Al1,
               const uint32_t* __restrict__ Bh1, const uint32_t* __restrict__ Bl1,
               int lda, size_t sA, size_t sB,
               float* __restrict__ C0, float* __restrict__ C1, size_t sC,
               uint32_t* __restrict__ Ph0, uint32_t* __restrict__ Pl0,
               uint32_t* __restrict__ Ph1, uint32_t* __restrict__ Pl1, size_t sP,
               int K, float outScale, float packScale)
{
    extern __shared__ __align__(16) uint32_t sm[];
    const int tid = threadIdx.x;
    const int bx = blockIdx.x, by = blockIdx.y;
    const int zraw = blockIdx.z;
    const bool sec = (zraw >= B_);
    const int bz = sec ? zraw - B_ : zraw;

    const uint32_t* Ah = sec ? Ah1 : Ah0;
    const uint32_t* Al = sec ? Al1 : Al0;
    const uint32_t* Bh = sec ? Bh1 : Bh0;
    const uint32_t* Bl = sec ? Bl1 : Bl0;
    float* C = sec ? C1 : C0;
    uint32_t* Ph = sec ? Ph1 : Ph0;
    uint32_t* Pl = sec ? Pl1 : Pl0;

    const uint32_t* gAh = Ah + (size_t)bz * sA + by * 128;
    const uint32_t* gAl = Al + (size_t)bz * sA + by * 128;
    const uint32_t* gBh = Bh + (size_t)bz * sB + bx * 128;
    const uint32_t* gBl = Bl + (size_t)bz * sB + bx * 128;

    const int lane = tid & 31, w = tid >> 5;
    const int g = lane >> 2, t = lane & 3;
    const int rbase = (w & 1) * 64;
    const int cbase = (w >> 1) * 32;

    const uint32_t smb = smem_u32(sm);
    const int srow = tid >> 4;
    const int scol = (tid & 15) * 8;

    float c[4][4][4];
#pragma unroll
    for (int i = 0; i < 4; ++i)
#pragma unroll
        for (int j = 0; j < 4; ++j)
#pragma unroll
            for (int k = 0; k < 4; ++k) c[i][j][k] = 0.f;

    const int T = K >> 5;
    const uint32_t doff = (uint32_t)(srow * SROW + scol) * 4;

#define STAGE_LOADS(sidx, kp0) do {                                             \
    const uint32_t base_ = smb + (uint32_t)(sidx) * (STG_U * 4);                \
    const size_t kr_ = (size_t)((kp0) + srow);                                  \
    CPA16(base_ + doff,                    gAh + kr_ * lda + scol);             \
    CPA16(base_ + doff + 16,               gAh + kr_ * lda + scol + 4);         \
    CPA16(base_ + TILE_U*4 + doff,         gAl + kr_ * lda + scol);             \
    CPA16(base_ + TILE_U*4 + doff + 16,    gAl + kr_ * lda + scol + 4);         \
    CPA16(base_ + 2*TILE_U*4 + doff,       gBh + kr_ * 512 + scol);             \
    CPA16(base_ + 2*TILE_U*4 + doff + 16,  gBh + kr_ * 512 + scol + 4);         \
    CPA16(base_ + 3*TILE_U*4 + doff,       gBl + kr_ * 512 + scol);             \
    CPA16(base_ + 3*TILE_U*4 + doff + 16,  gBl + kr_ * 512 + scol + 4);         \
} while (0)

#pragma unroll
    for (int s = 0; s < 3; ++s) {
        STAGE_LOADS(s, s * 16);
        CP_COMMIT();
    }

    int buf = 0;
    for (int tt = 0; tt < T; ++tt) {
        CP_WAIT1();
        __syncthreads();

        const uint32_t* Ahs = sm + buf * STG_U;
        const uint32_t* Als = Ahs + TILE_U;
        const uint32_t* Bhs = Als + TILE_U;
        const uint32_t* Bls = Bhs + TILE_U;
#pragma unroll
        for (int ks = 0; ks < 2; ++ks) {
            const int kr = ks * 8 + t;
            const uint32_t* aph = Ahs + kr * SROW;
            const uint32_t* apl = Als + kr * SROW;
            const uint32_t* bph = Bhs + kr * SROW;
            const uint32_t* bpl = Bls + kr * SROW;
            uint32_t ah[4][4], al[4][4], bh[4][2], bl[4][2];
#pragma unroll
            for (int i = 0; i < 4; ++i) {
                const int m = rbase + i * 16 + g;
                ah[i][0] = aph[m];            al[i][0] = apl[m];
                ah[i][1] = aph[m + 8];        al[i][1] = apl[m + 8];
                ah[i][2] = aph[4*SROW + m];   al[i][2] = apl[4*SROW + m];
                ah[i][3] = aph[4*SROW + m+8]; al[i][3] = apl[4*SROW + m+8];
            }
#pragma unroll
            for (int j = 0; j < 4; ++j) {
                const int n = cbase + j * 8 + g;
                bh[j][0] = bph[n];            bl[j][0] = bpl[n];
                bh[j][1] = bph[4*SROW + n];   bl[j][1] = bpl[4*SROW + n];
            }
#pragma unroll
            for (int i = 0; i < 4; ++i)
#pragma unroll
                for (int j = 0; j < 4; ++j) {
                    mma16(c[i][j], ah[i], bl[j]);
                    mma16(c[i][j], al[i], bh[j]);
                    mma16(c[i][j], ah[i], bh[j]);
                }
        }
        __syncthreads();

        if (tt + 3 < T) STAGE_LOADS(buf, (tt + 3) * 16);
        CP_COMMIT();
        buf = (buf == 2) ? 0 : buf + 1;
    }
#undef STAGE_LOADS

    if (EPI & 1) {
        const size_t coff = (size_t)bz * sC + (size_t)(by * 128) * 512 + bx * 128;
#pragma unroll
        for (int i = 0; i < 4; ++i) {
            const int r0 = rbase + i * 16 + g;
#pragma unroll
            for (int j = 0; j < 4; ++j) {
                const int cc = cbase + j * 8 + 2 * t;
                *reinterpret_cast<float2*>(C + coff + (size_t)r0 * 512 + cc) =
                    make_float2(c[i][j][0] * outScale, c[i][j][1] * outScale);
                *reinterpret_cast<float2*>(C + coff + (size_t)(r0 + 8) * 512 + cc) =
                    make_float2(c[i][j][2] * outScale, c[i][j][3] * outScale);
            }
        }
    }
    if (EPI & 2) {
        float* cs = reinterpret_cast<float*>(sm);
#pragma unroll
        for (int i = 0; i < 4; ++i) {
            const int r0 = rbase + i * 16 + g;
#pragma unroll
            for (int j = 0; j < 4; ++j) {
                const int cc = cbase + j * 8 + 2 * t;
                *reinterpret_cast<float2*>(cs + r0 * 132 + cc) =
                    make_float2(c[i][j][0], c[i][j][1]);
                *reinterpret_cast<float2*>(cs + (r0 + 8) * 132 + cc) =
                    make_float2(c[i][j][2], c[i][j][3]);
            }
        }
        __syncthreads();
        const size_t poff = (size_t)bz * sP + (size_t)(by * 64) * 512 + bx * 128;
#pragma unroll 4
        for (int it = 0; it < 32; ++it) {
            const int idx = it * 256 + tid;
            const int kp = idx >> 7, cc2 = idx & 127;
            const float x0 = cs[(2 * kp) * 132 + cc2] * packScale;
            const float x1 = cs[(2 * kp + 1) * 132 + cc2] * packScale;
            uint32_t u0, u1;
            pack2(x0, x1, u0, u1);
            Ph[poff + (size_t)kp * 512 + cc2] = u0;
            Pl[poff + (size_t)kp * 512 + cc2] = u1;
        }
    }
}

// ---- dual/transpose pack body ---------------------------------------------
__device__ __forceinline__ void dp_body(
    const float* __restrict__ src, int R, int C, int x0, int y0, size_t so,
    uint32_t* __restrict__ sh0, uint32_t* __restrict__ sh1, size_t sSd,
    uint32_t* __restrict__ th0, uint32_t* __restrict__ th1, size_t sTd, int bz)
{
    __shared__ float tile[32][33];
    for (int j = threadIdx.y; j < 32; j += 8)
        tile[j][threadIdx.x] = src[so + (size_t)(y0 + j) * C + x0 + threadIdx.x];
    __syncthreads();
    const int tx = threadIdx.x;
    for (int kpl = threadIdx.y; kpl < 16; kpl += 8) {
        uint32_t u0, u1;
        if (sh0) {
            pack2(tile[2 * kpl][tx], tile[2 * kpl + 1][tx], u0, u1);
            size_t o = (size_t)bz * sSd + (size_t)(y0 / 2 + kpl) * C + x0 + tx;
            sh0[o] = u0; sh1[o] = u1;
        }
        pack2(tile[tx][2 * kpl], tile[tx][2 * kpl + 1], u0, u1);
        size_t o = (size_t)bz * sTd + (size_t)(x0 / 2 + kpl) * R + y0 + tx;
        th0[o] = u0; th1[o] = u1;
    }
}

// ---- merged Q+V dual pack: grid (4096, B_), block (32, 8) -----------------
__global__ void pack_inputs_k(const float* __restrict__ Q,
                              uint32_t* Qp, uint32_t* Qph, uint32_t* Qtp, uint32_t* Qtph,
                              const float* __restrict__ V,
                              uint32_t* Vp, uint32_t* Vph, uint32_t* Vtp, uint32_t* Vtph)
{
    const int id = blockIdx.x, bz = blockIdx.y;
    if (id < 2048) {   // Q: R=NQ, C=H
        const int x0 = (id & 31) * 32, y0 = (id >> 5) * 32;
        dp_body(Q, NQ_, H_, x0, y0, (size_t)bz * NQ_ * H_,
                Qp, Qph, PQ, Qtp, Qtph, PQT, bz);
    } else {           // V: R=H, C=NV
        const int id2 = id - 2048;
        const int x0 = (id2 & 63) * 32, y0 = (id2 >> 6) * 32;
        dp_body(V, H_, NV_, x0, y0, (size_t)bz * H_ * NV_,
                Vp, Vph, PV, Vtp, Vtph, PVT, bz);
    }
}

// ---- merged weight packs: grid (2048), block (32, 8) ----------------------
__global__ void pack_weights_k(const float* __restrict__ W_b,
                               uint32_t* Wbp, uint32_t* Wbph, uint32_t* Wbtp, uint32_t* Wbtph,
                               const float* __restrict__ W_q, uint32_t* WqTp, uint32_t* WqTph,
                               const float* __restrict__ W_v, uint32_t* WvTp, uint32_t* WvTph)
{
    const int id = blockIdx.x;
    if (id < 1024) {            // Wb dual
        const int x0 = (id & 31) * 32, y0 = (id >> 5) * 32;
        dp_body(W_b, H_, H_, x0, y0, 0, Wbp, Wbph, 0, Wbtp, Wbtph, 0, 0);
    } else if (id < 1536) {     // WqT tpack
        const int id2 = id - 1024;
        const int x0 = (id2 & 31) * 32, y0 = (id2 >> 5) * 32;
        dp_body(W_q, CO_, H_, x0, y0, 0, nullptr, nullptr, 0, WqTp, WqTph, 0, 0);
    } else {                    // WvT
        const int id2 = id - 1536;
        const int x0 = (id2 & 31) * 32, y0 = (id2 >> 5) * 32;
        dp_body(W_v, CO_, H_, x0, y0, 0, nullptr, nullptr, 0, WvTp, WvTph, 0, 0);
    }
}

// ---- merged logits: z=0 -> set0, z=1 -> set1 ------------------------------
__global__ void logits_t2(const float* __restrict__ X0, const float* __restrict__ Y0,
                          const float* __restrict__ w0, float* __restrict__ lg0,
                          const float* __restrict__ X1, const float* __restrict__ Y1,
                          const float* __restrict__ w1, float* __restrict__ lg1,
                          int Ncol)
{
    const bool sec = (blockIdx.z != 0);
    const float* X = sec ? X1 : X0;
    const float* Y = sec ? Y1 : Y0;
    const float* w = sec ? w1 : w0;
    float* lg = sec ? lg1 : lg0;
    const int b = blockIdx.y;
    const int n = blockIdx.x * 8 + (threadIdx.x >> 5);
    const int lane = threadIdx.x & 31;
    const float* xp = X + ((size_t)b * Ncol + n) * CO_;
    const float* yp = Y + ((size_t)b * Ncol + n) * CO_;
    float acc = 0.f;
#pragma unroll 4
    for (int c = lane; c < CO_; c += 32)
        acc += w[c] * tanhf(xp[c] + yp[c]);
#pragma unroll
    for (int off = 16; off > 0; off >>= 1)
        acc += __shfl_down_sync(0xffffffffu, acc, off);
    if (lane == 0) lg[(size_t)b * Ncol + n] = acc;
}

// ---- merged softmax -------------------------------------------------------
__global__ void softmax2(const float* __restrict__ lg0, float* __restrict__ o0,
                         const float* __restrict__ lg1, float* __restrict__ o1,
                         int Ncol)
{
    __shared__ float buf[2048];
    __shared__ float red[256];
    const bool sec = (blockIdx.x >= B_);
    const int b = sec ? blockIdx.x - B_ : blockIdx.x;
    const float* x = (sec ? lg1 : lg0) + (size_t)b * Ncol;
    float* outp = (sec ? o1 : o0) + (size_t)b * Ncol;
    const int tid = threadIdx.x;
    float mx = -INFINITY;
    for (int i = tid; i < Ncol; i += 256) { float v = x[i]; buf[i] = v; mx = fmaxf(mx, v); }
    red[tid] = mx; __syncthreads();
    for (int s = 128; s > 0; s >>= 1) { if (tid < s) red[tid] = fmaxf(red[tid], red[tid + s]); __syncthreads(); }
    mx = red[0]; __syncthreads();
    float sm = 0.f;
    for (int i = tid; i < Ncol; i += 256) { float e = expf(buf[i] - mx); buf[i] = e; sm += e; }
    red[tid] = sm; __syncthreads();
    for (int s = 128; s > 0; s >>= 1) { if (tid < s) red[tid] += red[tid + s]; __syncthreads(); }
    const float inv = 1.f / red[0];
    for (int i = tid; i < Ncol; i += 256) outp[i] = buf[i] * inv;
}

// ---- merged weighted sums: z=0 -> v = a_v·V^T; z=1 -> q from packed Qt ----
__global__ void wdot2(const float* __restrict__ a_v, const float* __restrict__ V,
                      float* __restrict__ out_v,
                      const float* __restrict__ a_q, const uint32_t* __restrict__ Qtp,
                      const uint32_t* __restrict__ Qtph, float* __restrict__ out_q)
{
    const int b = blockIdx.y;
    const int w = threadIdx.x >> 5, lane = threadIdx.x & 31;
    if (blockIdx.z == 0) {
        const int h = blockIdx.x * 8 + w;
        const float* row = V + ((size_t)b * H_ + h) * NV_;
        const float* av = a_v + (size_t)b * NV_;
        float acc = 0.f;
        for (int i = lane; i < NV_; i += 32) acc += av[i] * row[i];
#pragma unroll
        for (int off = 16; off > 0; off >>= 1) acc += __shfl_down_sync(0xffffffffu, acc, off);
        if (lane == 0) out_v[(size_t)b * H_ + h] = acc;
    } else {
        if (blockIdx.x >= 64) return;
        const int kp = blockIdx.x * 8 + w;          // h pair: 2kp, 2kp+1
        const uint32_t* r0 = Qtp + (size_t)b * PQT + (size_t)kp * NQ_;
        const uint32_t* r1 = Qtph + (size_t)b * PQT + (size_t)kp * NQ_;
        const float* aq = a_q + (size_t)b * NQ_;
        float acc0 = 0.f, acc1 = 0.f;
        for (int q = lane; q < NQ_; q += 32) {
            const float2 f0 = __half22float2(*reinterpret_cast<const __half2*>(&r0[q]));
            const float2 f1 = __half22float2(*reinterpret_cast<const __half2*>(&r1[q]));
            const float a = aq[q];
            acc0 += a * (f0.x + f1.x);
            acc1 += a * (f0.y + f1.y);
        }
#pragma unroll
        for (int off = 16; off > 0; off >>= 1) {
            acc0 += __shfl_down_sync(0xffffffffu, acc0, off);
            acc1 += __shfl_down_sync(0xffffffffu, acc1, off);
        }
        if (lane == 0) {
            out_q[(size_t)b * H_ + 2 * kp]     = acc0;
            out_q[(size_t)b * H_ + 2 * kp + 1] = acc1;
        }
    }
}

// ---------------------------------------------------------------------------
extern "C" void kernel_launch(void* const* d_in, const int* in_sizes, int n_in,
                              void* d_out, int out_size)
{
    const float* V    = (const float*)d_in[0];
    const float* Q    = (const float*)d_in[1];
    const float* W_b  = (const float*)d_in[2];
    const float* W_v  = (const float*)d_in[3];
    const float* W_q  = (const float*)d_in[4];
    const float* w_hv = (const float*)d_in[5];
    const float* w_hq = (const float*)d_in[6];
    float* out = (float*)d_out;

#define USYM(p, s) uint32_t* p; cudaGetSymbolAddress((void**)&p, s)
#define FSYM(p, s) float* p;    cudaGetSymbolAddress((void**)&p, s)
    USYM(Qp, g_Qp);     USYM(Qph, g_Qph);
    USYM(Qtp, g_Qtp);   USYM(Qtph, g_Qtph);
    USYM(Vp, g_Vp);     USYM(Vph, g_Vph);
    USYM(Vtp, g_Vtp);   USYM(Vtph, g_Vtph);
    USYM(Wbp, g_Wbp);   USYM(Wbph, g_Wbph);
    USYM(Wbtp, g_Wbtp); USYM(Wbtph, g_Wbtph);
    USYM(WqTp, g_WqTp); USYM(WqTph, g_WqTph);
    USYM(WvTp, g_WvTp); USYM(WvTph, g_WvTph);
    USYM(T1p, g_T1p);   USYM(T1ph, g_T1ph);
    USYM(T2p, g_T2p);   USYM(T2ph, g_T2ph);
    USYM(PvTp, g_PvTp); USYM(PvTph, g_PvTph);
    USYM(PqTp, g_PqTp); USYM(PqTph, g_PqTph);
    USYM(RvTp, g_RvTp); USYM(RvTph, g_RvTph);
    USYM(RqTp, g_RqTp); USYM(RqTph, g_RqTph);
    FSYM(T1, g_T1);   FSYM(T2, g_T2);
    FSYM(MvT, g_MvT); FSYM(MqT, g_MqT);
    FSYM(logv, g_logv); FSYM(logq, g_logq);
#undef USYM
#undef FSYM

    cudaFuncSetAttribute(gemm_pair<1>, cudaFuncAttributeMaxDynamicSharedMemorySize, SMEM_MMA);
    cudaFuncSetAttribute(gemm_pair<2>, cudaFuncAttributeMaxDynamicSharedMemorySize, SMEM_MMA);
    cudaFuncSetAttribute(gemm_pair<3>, cudaFuncAttributeMaxDynamicSharedMemorySize, SMEM_MMA);

    const size_t sNC = (size_t)NQ_ * CO_;
    const float S = 0.0625f;
    const float R16 = 16.0f;

    // pre-pass: 2 launches
    pack_inputs_k<<<dim3(4096, B_), dim3(32, 8)>>>(Q, Qp, Qph, Qtp, Qtph,
                                                   V, Vp, Vph, Vtp, Vtph);
    pack_weights_k<<<2048, dim3(32, 8)>>>(W_b, Wbp, Wbph, Wbtp, Wbtph,
                                          W_q, WqTp, WqTph, W_v, WvTp, WvTph);

    // pair1: G1 T1 = Qt^T·WqT | G2 T2 = V^T·WvT   [2048,512] K=1024  (fp32 + packed)
    gemm_pair<3><<<dim3(4, NQ_/128, 2*B_), 256, SMEM_MMA>>>(
        Qtp, Qtph, WqTp, WqTph,   Vp, Vph, WvTp, WvTph,
        2048, PQT, 0,  T1, T2, sNC,  T1p, T1ph, T2p, T2ph, PNC,  H_, 1.f, S);
    // pair2: G3 PvT = Q^T·T1 | G6 PqT = Vt^T·T2   [1024,512] K=2048
    gemm_pair<2><<<dim3(4, H_/128, 2*B_), 256, SMEM_MMA>>>(
        Qp, Qph, T1p, T1ph,   Vtp, Vtph, T2p, T2ph,
        1024, PQ, PNC,  nullptr, nullptr, 0,  PvTp, PvTph, PqTp, PqTph, PHC,  NQ_, R16, 1.f);
    // pair3: G4 RvT = Wb^T·PvT | G7 RqT = Wbt^T·PqT [1024,512] K=1024
    gemm_pair<2><<<dim3(4, H_/128, 2*B_), 256, SMEM_MMA>>>(
        Wbp, Wbph, PvTp, PvTph,   Wbtp, Wbtph, PqTp, PqTph,
        1024, 0, PHC,  nullptr, nullptr, 0,  RvTp, RvTph, RqTp, RqTph, PHC,  H_, R16, 1.f);
    // pair4: G5 MvT = V^T·RvT | G8 MqT = Qt^T·RqT  [2048,512] K=1024  (fp32 only)
    gemm_pair<1><<<dim3(4, NV_/128, 2*B_), 256, SMEM_MMA>>>(
        Vp, Vph, RvTp, RvTph,   Qtp, Qtph, RqTp, RqTph,
        2048, PV, PHC,  MvT, MqT, sNC,  nullptr, nullptr, nullptr, nullptr, 0,  H_, R16, 0.f);

    logits_t2<<<dim3(NV_/8, B_, 2), 256>>>(T2, MvT, w_hv, logv, T1, MqT, w_hq, logq, NV_);

    float* out_av = out;
    float* out_aq = out + (size_t)B_ * NV_;
    float* out_v  = out + (size_t)B_ * (NV_ + NQ_);
    float* out_q  = out_v + (size_t)B_ * H_;

    softmax2<<<2 * B_, 256>>>(logv, out_av, logq, out_aq, NV_);
    wdot2<<<dim3(H_/8, B_, 2), 256>>>(out_av, V, out_v, out_aq, Qtp, Qtph, out_q);
}